// round 3
// baseline (speedup 1.0000x reference)
#include <cuda_runtime.h>

// 8-qubit batched circuit simulator, warp-per-element.
// k = lane*8 + j ; wire w <-> bit (7-w) of k.
//   wires 0..4 -> lane bits 4..0 ; wires 5..7 -> j bits 2..0.

#define NQ 8
#define DIM 256
#define WPB 8                 // warps per block
#define THREADS (WPB * 32)
#define FULL 0xffffffffu

__global__ __launch_bounds__(THREADS)
void qsim_kernel(const float* __restrict__ x,
                 const float* __restrict__ theta,
                 float* __restrict__ out, int B)
{
    __shared__ float2 gsm[2][8][4];        // Rot gate matrices [layer][wire][g00,g01,g10,g11]
    __shared__ unsigned char perm[2][256]; // composed CNOT-ring permutations
    __shared__ float2 stage[WPB][256];     // per-warp permutation staging

    const int tid = threadIdx.x;

    // ---- precompute gate matrices (16 threads) ----
    if (tid < 16) {
        int l = tid >> 3, w = tid & 7;
        const float* t = theta + (l * 8 + w) * 3;
        float phi = t[0], th = t[1], om = t[2];
        float s, c;   sincosf(0.5f * th,        &s,  &c);
        float sa, ca; sincosf(0.5f * (phi + om), &sa, &ca);
        float sb, cb; sincosf(0.5f * (phi - om), &sb, &cb);
        // g00 = e^{-i(phi+om)/2} c ; g01 = -e^{+i(phi-om)/2} s
        // g10 = e^{-i(phi-om)/2} s ; g11 = e^{+i(phi+om)/2} c
        gsm[l][w][0] = make_float2( ca * c, -sa * c);
        gsm[l][w][1] = make_float2(-cb * s, -sb * s);
        gsm[l][w][2] = make_float2( cb * s, -sb * s);
        gsm[l][w][3] = make_float2( ca * c,  sa * c);
    }

    // ---- precompute ring permutations (256 threads) ----
    // s_after[k] = s_before[L1(L2(...L8(k)))], CNOT i: ctrl=w=i-1, tgt=(w+r)%8
    // L_w(m) = m XOR (bit_{7-w}(m) << (7-((w+r)%8)))
    {
        for (int ring = 0; ring < 2; ring++) {
            int r = ring + 1;
            int m = tid;
            for (int w = 7; w >= 0; w--) {
                int pc = 7 - w;
                int pt = 7 - ((w + r) & 7);
                m ^= ((m >> pc) & 1) << pt;
            }
            perm[ring][tid] = (unsigned char)m;
        }
    }
    __syncthreads();

    const int warp = tid >> 5;
    const int lane = tid & 31;
    const int e = blockIdx.x * WPB + warp;
    if (e >= B) return;   // whole warp exits together

    // ---- embedding: product state from RX angles ----
    float xv = x[e * 8 + (lane & 7)];
    float sv, cv;
    sincosf(0.5f * xv, &sv, &cv);
    float cw[8], sw[8];
#pragma unroll
    for (int w = 0; w < 8; w++) {
        cw[w] = __shfl_sync(FULL, cv, w);
        sw[w] = __shfl_sync(FULL, sv, w);
    }
    float ml = 1.f;
#pragma unroll
    for (int w = 0; w < 5; w++)
        ml *= ((lane >> (4 - w)) & 1) ? sw[w] : cw[w];
    const int pl = __popc(lane);

    float ar[8], ai[8];
#pragma unroll
    for (int j = 0; j < 8; j++) {
        float m = ml * ((j & 4) ? sw[5] : cw[5])
                     * ((j & 2) ? sw[6] : cw[6])
                     * ((j & 1) ? sw[7] : cw[7]);
        int p = (pl + __popc(j)) & 3;   // (-i)^p phase
        ar[j] = (p == 0) ? m : ((p == 2) ? -m : 0.f);
        ai[j] = (p == 1) ? -m : ((p == 3) ? m : 0.f);
    }

    // ---- two entangling layers ----
#pragma unroll
    for (int layer = 0; layer < 2; layer++) {
#pragma unroll
        for (int w = 0; w < 8; w++) {
            const float2 g00 = gsm[layer][w][0];
            const float2 g01 = gsm[layer][w][1];
            const float2 g10 = gsm[layer][w][2];
            const float2 g11 = gsm[layer][w][3];
            if (w < 5) {
                // wire lives in lane bits -> shuffle butterfly
                const int lm  = 1 << (4 - w);
                const int myb = (lane >> (4 - w)) & 1;
                const float gr = myb ? g11.x : g00.x;
                const float gi = myb ? g11.y : g00.y;
                const float hr = myb ? g10.x : g01.x;
                const float hi = myb ? g10.y : g01.y;
#pragma unroll
                for (int j = 0; j < 8; j++) {
                    float orr = __shfl_xor_sync(FULL, ar[j], lm);
                    float oii = __shfl_xor_sync(FULL, ai[j], lm);
                    float nr = gr * ar[j] - gi * ai[j] + hr * orr - hi * oii;
                    float ni = gr * ai[j] + gi * ar[j] + hr * oii + hi * orr;
                    ar[j] = nr; ai[j] = ni;
                }
            } else {
                // wire lives in register bits -> local butterfly
                const int bm = 1 << (7 - w);   // 4, 2, 1
#pragma unroll
                for (int j0 = 0; j0 < 8; j0++) {
                    if (j0 & bm) continue;
                    int j1 = j0 | bm;
                    float a_r = ar[j0], a_i = ai[j0];
                    float b_r = ar[j1], b_i = ai[j1];
                    ar[j0] = g00.x * a_r - g00.y * a_i + g01.x * b_r - g01.y * b_i;
                    ai[j0] = g00.x * a_i + g00.y * a_r + g01.x * b_i + g01.y * b_r;
                    ar[j1] = g10.x * a_r - g10.y * a_i + g11.x * b_r - g11.y * b_i;
                    ai[j1] = g10.x * a_i + g10.y * a_r + g11.x * b_i + g11.y * b_r;
                }
            }
        }
        // ---- CNOT ring as one permutation via smem staging ----
#pragma unroll
        for (int j = 0; j < 8; j++)
            stage[warp][j * 32 + lane] = make_float2(ar[j], ai[j]);
        __syncwarp();
#pragma unroll
        for (int j = 0; j < 8; j++) {
            int k  = lane * 8 + j;
            int kp = perm[layer][k];
            float2 v = stage[warp][(kp & 7) * 32 + (kp >> 3)];
            ar[j] = v.x; ai[j] = v.y;
        }
        __syncwarp();
    }

    // ---- expval(Z0): sign by bit7 of k = bit4 of lane ----
    float acc = 0.f;
#pragma unroll
    for (int j = 0; j < 8; j++)
        acc += ar[j] * ar[j] + ai[j] * ai[j];
    if (lane & 16) acc = -acc;
#pragma unroll
    for (int off = 16; off; off >>= 1)
        acc += __shfl_down_sync(FULL, acc, off);
    if (lane == 0) out[e] = (acc + 1.f) * 0.5f;
}

extern "C" void kernel_launch(void* const* d_in, const int* in_sizes, int n_in,
                              void* d_out, int out_size)
{
    const float* x     = (const float*)d_in[0];
    const float* theta = (const float*)d_in[1];
    // defensive: theta has 48 elements, x has B*8
    if (n_in >= 2 && in_sizes[0] == 48) {
        const float* tmp = x; x = theta; theta = tmp;
    }
    int B = out_size;  // one output per element
    int blocks = (B + WPB - 1) / WPB;
    qsim_kernel<<<blocks, THREADS>>>(x, theta, (float*)d_out, B);
}

// round 7
// speedup vs baseline: 26.8631x; 26.8631x over previous
#include <cuda_runtime.h>

// Heisenberg-picture evaluation of the 8-qubit, 2-layer circuit.
// ev = sum over 27 Pauli strings of kappa_mu * prod_w D_w[code(mu,w)].
// All Clifford (CNOT-ring) structure is resolved at compile time.

#define TPB 256

// ---------------- compile-time Pauli machinery ----------------
// mu in [0,27): slot paulis p2 = mu/9, p4 = (mu/3)%3, p6 = mu%3 ; 0=X,1=Y,2=Z.
// Returns: bits [2w,2w+1] = pauli code of wire w in ring1-conjugated string
// (0=I,1=X,2=Y,3=Z); bit 16 = sign (1 -> negative).
constexpr __host__ __device__ unsigned conj_pack(int mu) {
    int a[8] = {}, b[8] = {};
    int tph = 0;                       // initial #Y (phase i^tph in XZ rep)
    const int p[3] = { mu / 9, (mu / 3) % 3, mu % 3 };
    const int ws[3] = { 2, 4, 6 };
    for (int i = 0; i < 3; i++) {
        int q = p[i], w = ws[i];
        if (q == 0)      { a[w] = 1; }                  // X
        else if (q == 1) { a[w] = 1; b[w] = 1; tph++; } // Y = i X Z
        else             { b[w] = 1; }                  // Z
    }
    // Ring1 (r=1): state-order gates w=0..7, conjugate outermost-first g=7..0.
    // CNOT(c,t): X_c->X_cX_t, Z_t->Z_cZ_t (no reorder signs in XZ rep).
    for (int g = 7; g >= 0; g--) {
        int c = g, t = (g + 1) & 7;
        a[t] ^= a[c];
        b[c] ^= b[t];
    }
    unsigned pack = 0; int ny = 0;
    for (int w = 0; w < 8; w++) {
        int code = a[w] ? (b[w] ? 2 : 1) : (b[w] ? 3 : 0);
        if (code == 2) ny++;
        pack |= (unsigned)code << (2 * w);
    }
    int sg = ((tph - ny) % 4 + 4) % 4;     // 0 or 2 for a Hermitian result
    if (sg == 2) pack |= (1u << 16);
    return pack;
}

// runtime-readable copy (for the kappa sign)
__device__ const unsigned d_pk[27] = {
    conj_pack(0),  conj_pack(1),  conj_pack(2),  conj_pack(3),  conj_pack(4),
    conj_pack(5),  conj_pack(6),  conj_pack(7),  conj_pack(8),  conj_pack(9),
    conj_pack(10), conj_pack(11), conj_pack(12), conj_pack(13), conj_pack(14),
    conj_pack(15), conj_pack(16), conj_pack(17), conj_pack(18), conj_pack(19),
    conj_pack(20), conj_pack(21), conj_pack(22), conj_pack(23), conj_pack(24),
    conj_pack(25), conj_pack(26)
};

// ---- fully unrolled accumulation with compile-time register indexing ----
template<unsigned PKC, int W>
__device__ __forceinline__ float mulw(float t, const float (&D)[8][3]) {
    if constexpr (W == 8) {
        return t;
    } else {
        constexpr int c = (PKC >> (2 * W)) & 3;
        if constexpr (c != 0) t *= D[W][c - 1];
        return mulw<PKC, W + 1>(t, D);
    }
}

template<int MU>
__device__ __forceinline__ void accall(float& ev, const float* kap,
                                       const float (&D)[8][3]) {
    if constexpr (MU < 27) {
        constexpr unsigned pk = conj_pack(MU);
        static_assert((pk >> 16) <= 1, "sign must be +/-1");
        constexpr unsigned pkc = pk & 0xFFFFu;  // sign folded into kap
        ev += mulw<pkc, 0>(kap[MU], D);
        accall<MU + 1>(ev, kap, D);
    }
}

// ---------------- kernel ----------------
__global__ __launch_bounds__(TPB)
void qev_kernel(const float* __restrict__ x, const float* __restrict__ theta,
                float* __restrict__ out, int B)
{
    // Rot SO(3) rows, layer 1 (only Y/Z columns needed: <X>=0):
    //   O[X] = ( cw*ct*cp - sw*sp , -cw*ct*sp - sw*cp , cw*st )
    //   O[Y] = ( sw*ct*cp + cw*sp , -sw*ct*sp + cw*cp , sw*st )
    //   O[Z] = ( -st*cp           ,  st*sp            , ct    )
    __shared__ float Es[8][3][2];  // [wire][pauli X/Y/Z][Ycoef, Zcoef]
    __shared__ float zr[3][3];     // layer-2 Z-rows, wires {2,4,6} x {X,Y,Z}
    __shared__ float kap[27];

    const int tid = threadIdx.x;
    if (tid < 8) {
        const float* t = theta + tid * 3;            // layer 0
        float sp, cp, st, ct, sw, cw;
        sincosf(t[0], &sp, &cp);
        sincosf(t[1], &st, &ct);
        sincosf(t[2], &sw, &cw);
        Es[tid][0][0] = -cw * ct * sp - sw * cp;  Es[tid][0][1] = cw * st;
        Es[tid][1][0] = -sw * ct * sp + cw * cp;  Es[tid][1][1] = sw * st;
        Es[tid][2][0] =  st * sp;                 Es[tid][2][1] = ct;
    } else if (tid < 11) {
        int i = tid - 8;
        const float* t = theta + 24 + (2 + 2 * i) * 3;  // layer 1, wire 2/4/6
        float sp, cp, st, ct;
        sincosf(t[0], &sp, &cp);
        sincosf(t[1], &st, &ct);
        zr[i][0] = -st * cp;
        zr[i][1] =  st * sp;
        zr[i][2] =  ct;
    }
    __syncthreads();
    if (tid < 27) {
        float k = zr[0][tid / 9] * zr[1][(tid / 3) % 3] * zr[2][tid % 3];
        if (d_pk[tid] >> 16) k = -k;
        kap[tid] = k;
    }
    __syncthreads();

    const int e = blockIdx.x * TPB + tid;
    if (e >= B) return;

    const float4 xa = *(const float4*)(x + e * 8);
    const float4 xb = *(const float4*)(x + e * 8 + 4);
    const float xs[8] = { xa.x, xa.y, xa.z, xa.w, xb.x, xb.y, xb.z, xb.w };

    float D[8][3];
#pragma unroll
    for (int w = 0; w < 8; w++) {
        float s, c;
        __sincosf(xs[w], &s, &c);     // Bloch: <Y>=-sin x, <Z>=cos x
        float ny = -s;
#pragma unroll
        for (int p = 0; p < 3; p++)
            D[w][p] = fmaf(Es[w][p][0], ny, Es[w][p][1] * c);
    }

    float ev = 0.f;
    accall<0>(ev, kap, D);

    out[e] = (ev + 1.f) * 0.5f;
}

extern "C" void kernel_launch(void* const* d_in, const int* in_sizes, int n_in,
                              void* d_out, int out_size)
{
    const float* x     = (const float*)d_in[0];
    const float* theta = (const float*)d_in[1];
    if (n_in >= 2 && in_sizes[0] == 48) {   // defensive input-order swap
        const float* tmp = x; x = theta; theta = tmp;
    }
    int B = out_size;
    int blocks = (B + TPB - 1) / TPB;
    qev_kernel<<<blocks, TPB>>>(x, theta, (float*)d_out, B);
}

// round 9
// speedup vs baseline: 33.9664x; 1.2644x over previous
#include <cuda_runtime.h>

// Heisenberg-picture evaluation of the 8-qubit, 2-layer circuit.
// ev = sum over 27 Pauli strings of kappa_mu * prod_w D_w[code(mu,w)].
// All Clifford (CNOT-ring) structure is resolved at compile time.

#define TPB 128

// ---------------- compile-time Pauli machinery ----------------
// mu in [0,27): slot paulis p2 = mu/9, p4 = (mu/3)%3, p6 = mu%3 ; 0=X,1=Y,2=Z.
// Returns: bits [2w,2w+1] = pauli code of wire w in ring1-conjugated string
// (0=I,1=X,2=Y,3=Z); bit 16 = sign (1 -> negative).
constexpr __host__ __device__ unsigned conj_pack(int mu) {
    int a[8] = {}, b[8] = {};
    int tph = 0;                       // initial #Y (phase i^tph in XZ rep)
    const int p[3] = { mu / 9, (mu / 3) % 3, mu % 3 };
    const int ws[3] = { 2, 4, 6 };
    for (int i = 0; i < 3; i++) {
        int q = p[i], w = ws[i];
        if (q == 0)      { a[w] = 1; }                  // X
        else if (q == 1) { a[w] = 1; b[w] = 1; tph++; } // Y = i X Z
        else             { b[w] = 1; }                  // Z
    }
    // Ring1 (r=1): state-order gates w=0..7, conjugate outermost-first g=7..0.
    // CNOT(c,t): X_c->X_cX_t, Z_t->Z_cZ_t (no reorder signs in XZ rep).
    for (int g = 7; g >= 0; g--) {
        int c = g, t = (g + 1) & 7;
        a[t] ^= a[c];
        b[c] ^= b[t];
    }
    unsigned pack = 0; int ny = 0;
    for (int w = 0; w < 8; w++) {
        int code = a[w] ? (b[w] ? 2 : 1) : (b[w] ? 3 : 0);
        if (code == 2) ny++;
        pack |= (unsigned)code << (2 * w);
    }
    int sg = ((tph - ny) % 4 + 4) % 4;     // 0 or 2 for a Hermitian result
    if (sg == 2) pack |= (1u << 16);
    return pack;
}

// constant-bank copy (for the kappa sign at runtime)
__constant__ unsigned c_pk[27] = {
    conj_pack(0),  conj_pack(1),  conj_pack(2),  conj_pack(3),  conj_pack(4),
    conj_pack(5),  conj_pack(6),  conj_pack(7),  conj_pack(8),  conj_pack(9),
    conj_pack(10), conj_pack(11), conj_pack(12), conj_pack(13), conj_pack(14),
    conj_pack(15), conj_pack(16), conj_pack(17), conj_pack(18), conj_pack(19),
    conj_pack(20), conj_pack(21), conj_pack(22), conj_pack(23), conj_pack(24),
    conj_pack(25), conj_pack(26)
};

// ---- string product, fully unrolled, compile-time register indexing ----
// HAVE tracks whether t already holds a factor (avoids a 1.0f* seed mul).
template<unsigned PKC, int W, bool HAVE>
__device__ __forceinline__ float sprod(const float (&D)[8][3], float t) {
    if constexpr (W == 8) {
        return t;
    } else {
        constexpr int c = (PKC >> (2 * W)) & 3;
        if constexpr (c == 0) {
            return sprod<PKC, W + 1, HAVE>(D, t);
        } else if constexpr (HAVE) {
            return sprod<PKC, W + 1, true>(D, t * D[W][c - 1]);
        } else {
            return sprod<PKC, W + 1, true>(D, D[W][c - 1]);
        }
    }
}

template<int MU>
__device__ __forceinline__ void accall(float (&ev)[4], const float* kap,
                                       const float (&D)[8][3]) {
    if constexpr (MU < 27) {
        constexpr unsigned pk = conj_pack(MU);
        static_assert((pk & 0xFFFFu) != 0, "string must be non-identity");
        constexpr unsigned pkc = pk & 0xFFFFu;  // sign folded into kap
        float p = sprod<pkc, 0, false>(D, 0.f);
        ev[MU & 3] = fmaf(kap[MU], p, ev[MU & 3]);
        accall<MU + 1>(ev, kap, D);
    }
}

// ---------------- kernel ----------------
__global__ __launch_bounds__(TPB)
void qev_kernel(const float* __restrict__ x, const float* __restrict__ theta,
                float* __restrict__ out, int B)
{
    // Rot SO(3) rows (only Y/Z columns needed: <X>=0):
    //   O[X] = ( . , -cw*ct*sp - sw*cp , cw*st )
    //   O[Y] = ( . , -sw*ct*sp + cw*cp , sw*st )
    //   O[Z] = ( . ,  st*sp            , ct    )
    __shared__ float Es[8][3][2];  // [wire][pauli X/Y/Z][Ycoef, Zcoef]
    __shared__ float kap[27];

    const int tid = threadIdx.x;
    if (tid < 8) {
        // layer-0 per-wire conjugation coefficients (warp 0)
        const float* t = theta + tid * 3;
        float sp, cp, st, ct, sw, cw;
        __sincosf(t[0], &sp, &cp);
        __sincosf(t[1], &st, &ct);
        __sincosf(t[2], &sw, &cw);
        Es[tid][0][0] = -cw * ct * sp - sw * cp;  Es[tid][0][1] = cw * st;
        Es[tid][1][0] = -sw * ct * sp + cw * cp;  Es[tid][1][1] = sw * st;
        Es[tid][2][0] =  st * sp;                 Es[tid][2][1] = ct;
    } else if (tid >= 32 && tid < 59) {
        // kappa coefficients (warp 1, runs concurrently with warp 0)
        const int m = tid - 32;
        const int i2 = m / 9, i4 = (m / 3) % 3, i6 = m % 3;
        float k;
        {   // slot wire 2 (layer 1)
            const float* t = theta + 24 + 2 * 3;
            float sp, cp, st, ct;
            __sincosf(t[0], &sp, &cp);
            __sincosf(t[1], &st, &ct);
            k = (i2 == 0) ? (-st * cp) : ((i2 == 1) ? (st * sp) : ct);
        }
        {   // slot wire 4
            const float* t = theta + 24 + 4 * 3;
            float sp, cp, st, ct;
            __sincosf(t[0], &sp, &cp);
            __sincosf(t[1], &st, &ct);
            k *= (i4 == 0) ? (-st * cp) : ((i4 == 1) ? (st * sp) : ct);
        }
        {   // slot wire 6
            const float* t = theta + 24 + 6 * 3;
            float sp, cp, st, ct;
            __sincosf(t[0], &sp, &cp);
            __sincosf(t[1], &st, &ct);
            k *= (i6 == 0) ? (-st * cp) : ((i6 == 1) ? (st * sp) : ct);
        }
        if (c_pk[m] >> 16) k = -k;
        kap[m] = k;
    }
    __syncthreads();

    const int e = blockIdx.x * TPB + tid;
    if (e >= B) return;

    const float4 xa = *(const float4*)(x + e * 8);
    const float4 xb = *(const float4*)(x + e * 8 + 4);
    const float xs[8] = { xa.x, xa.y, xa.z, xa.w, xb.x, xb.y, xb.z, xb.w };

    float D[8][3];
#pragma unroll
    for (int w = 0; w < 8; w++) {
        float s, c;
        __sincosf(xs[w], &s, &c);     // Bloch: <Y>=-sin x, <Z>=cos x
        float ny = -s;
#pragma unroll
        for (int p = 0; p < 3; p++)
            D[w][p] = fmaf(Es[w][p][0], ny, Es[w][p][1] * c);
    }

    float ev[4] = { 0.f, 0.f, 0.f, 0.f };
    accall<0>(ev, kap, D);
    float e01 = ev[0] + ev[1], e23 = ev[2] + ev[3];

    out[e] = fmaf(0.5f, e01 + e23, 0.5f);
}

extern "C" void kernel_launch(void* const* d_in, const int* in_sizes, int n_in,
                              void* d_out, int out_size)
{
    const float* x     = (const float*)d_in[0];
    const float* theta = (const float*)d_in[1];
    if (n_in >= 2 && in_sizes[0] == 48) {   // defensive input-order swap
        const float* tmp = x; x = theta; theta = tmp;
    }
    int B = out_size;
    int blocks = (B + TPB - 1) / TPB;
    qev_kernel<<<blocks, TPB>>>(x, theta, (float*)d_out, B);
}